// round 14
// baseline (speedup 1.0000x reference)
#include <cuda_runtime.h>
#include <cuda_fp16.h>

#define NNZ        2000000
#define NUM_NODES  200000
#define NUM_EDGES  100000
#define HID        64
#define WE         96      // ELL row stride, edge->nodes (deg ~Poisson(20))
#define WN         64      // ELL row stride, node->edges (deg ~Poisson(10))

// ---------------- scratch (device globals; zero-initialized at load) -------
// Invariant: g_cntE, g_cntN are ZERO at the start of every kernel_launch
// (module-load zeros; re-zeroed by cleanup_kernel at the end of every launch).
__device__ __half g_x0[NUM_NODES * HID];    // fp16 copy of emb
__device__ __half g_x1[NUM_NODES * HID];
__device__ __half g_x2[NUM_NODES * HID];
__device__ __half g_gh[NUM_EDGES * HID];    // fp16 edge features after GEMM
__device__ float  g_eacc[NUM_EDGES * HID];  // fp32 node->edge accumulator
__device__ float  g_Dinv[NUM_NODES];
__device__ float  g_Binv[NUM_EDGES];
__device__ int    g_cntE[NUM_EDGES];
__device__ int    g_cntN[NUM_NODES];
__device__ int    g_csrE[NUM_EDGES * WE];   // node ids per edge (ELL)
__device__ int    g_csrN[NUM_NODES * WN];   // edge ids per node (ELL)

static inline int cdiv(int a, int b) { return (a + b - 1) / b; }

// ---------------- ELL build: counting-place in ONE pass --------------------
__global__ void fill_ell(const int* __restrict__ nidx,
                         const int* __restrict__ eidx) {
    int i = blockIdx.x * blockDim.x + threadIdx.x;
    if (i < NNZ) {
        int n = nidx[i];
        int e = eidx[i];
        int p = atomicAdd(&g_cntE[e], 1);
        if (p < WE) g_csrE[e * WE + p] = n;
        int q = atomicAdd(&g_cntN[n], 1);
        if (q < WN) g_csrN[n * WN + q] = e;
    }
}

// Dinv via ew-gather over node rows (8 lanes/node) + Binv from counts.
__global__ void deg_inv(const float* __restrict__ ew) {
    int t = blockIdx.x * blockDim.x + threadIdx.x;   // NUM_NODES*8 threads
    int n = t >> 3;
    int c = t & 7;
    int cnt = min(g_cntN[n], WN);
    float s = 0.f;
    for (int j = c; j < cnt; j += 8)
        s += __ldg(&ew[g_csrN[n * WN + j]]);
    #pragma unroll
    for (int off = 4; off; off >>= 1)
        s += __shfl_down_sync(0xFFFFFFFFu, s, off, 8);
    if (c == 0) g_Dinv[n] = s > 0.f ? 1.f / s : 0.f;
    if (t < NUM_EDGES) {
        int b = min(g_cntE[t], WE);
        g_Binv[t] = b > 0 ? 1.f / (float)b : 0.f;
    }
}

// emb fp32 -> x0 fp16 (one thread per 8 elements)
__global__ void convert_emb(const float4* __restrict__ emb4) {
    int i = blockIdx.x * blockDim.x + threadIdx.x;
    if (i < NUM_NODES * 8) {
        float4 u = __ldg(&emb4[2 * i]);
        float4 v = __ldg(&emb4[2 * i + 1]);
        __half2 h0 = __floats2half2_rn(u.x, u.y);
        __half2 h1 = __floats2half2_rn(u.z, u.w);
        __half2 h2 = __floats2half2_rn(v.x, v.y);
        __half2 h3 = __floats2half2_rn(v.z, v.w);
        uint4 o;
        o.x = *reinterpret_cast<unsigned*>(&h0);
        o.y = *reinterpret_cast<unsigned*>(&h1);
        o.z = *reinterpret_cast<unsigned*>(&h2);
        o.w = *reinterpret_cast<unsigned*>(&h3);
        reinterpret_cast<uint4*>(g_x0)[i] = o;
    }
}

// End-of-launch cleanup: restore the zero invariant for the next replay.
__global__ void cleanup_kernel() {
    int i = blockIdx.x * blockDim.x + threadIdx.x;
    if (i < NUM_EDGES) g_cntE[i] = 0;
    if (i < NUM_NODES) g_cntN[i] = 0;
}

// ---------------- gather core (fp16 rows, 8 lanes/row, ELL) ----------------
#define ACCH(A, B, v) {                                                   \
    __half2* hh = reinterpret_cast<__half2*>(&(v));                       \
    float2 f0 = __half22float2(hh[0]); float2 f1 = __half22float2(hh[1]); \
    float2 f2 = __half22float2(hh[2]); float2 f3 = __half22float2(hh[3]); \
    A.x += f0.x; A.y += f0.y; A.z += f1.x; A.w += f1.y;                   \
    B.x += f2.x; B.y += f2.y; B.z += f3.x; B.w += f3.y; }

// Lanes 0-3 load batch indices, broadcast via width-8 shfl; accumulation fp32.
__device__ __forceinline__ void gather_row_ell(const int* __restrict__ csr,
                                               int cnt,
                                               const uint4* __restrict__ src,
                                               int c, unsigned mask,
                                               float4& A, float4& B) {
    A = make_float4(0.f, 0.f, 0.f, 0.f);
    B = A;
    int k = 0;
    int my = 0;
    if (k + 4 <= cnt) {
        if (c < 4) my = __ldg(&csr[k + c]);
        while (k + 4 <= cnt) {
            int i0 = __shfl_sync(mask, my, 0, 8);
            int i1 = __shfl_sync(mask, my, 1, 8);
            int i2 = __shfl_sync(mask, my, 2, 8);
            int i3 = __shfl_sync(mask, my, 3, 8);
            int kn = k + 4;
            if (kn + 4 <= cnt && c < 4) my = __ldg(&csr[kn + c]);
            uint4 v0 = __ldg(src + i0 * 8);
            uint4 v1 = __ldg(src + i1 * 8);
            uint4 v2 = __ldg(src + i2 * 8);
            uint4 v3 = __ldg(src + i3 * 8);
            ACCH(A, B, v0); ACCH(A, B, v1); ACCH(A, B, v2); ACCH(A, B, v3);
            k = kn;
        }
    }
    for (; k < cnt; k++) {
        int i0 = __ldg(&csr[k]);
        uint4 v = __ldg(src + i0 * 8);
        ACCH(A, B, v);
    }
}

// node -> edge: eacc[e] (fp32) = sum of fp16 x rows
__global__ void __launch_bounds__(256) gather_ne_h(const __half* __restrict__ x) {
    int t = blockIdx.x * blockDim.x + threadIdx.x;
    int e = t >> 3;
    int c = t & 7;
    unsigned mask = 0xFFu << (threadIdx.x & 24);
    int cnt = min(g_cntE[e], WE);
    float4 A, B;
    gather_row_ell(&g_csrE[e * WE], cnt, (const uint4*)x + c, c, mask, A, B);
    float4* o = (float4*)g_eacc + e * 16 + c * 2;
    o[0] = A;
    o[1] = B;
}

// edge GEMM: g_gh[r][j] = fp16( ew[r] * ( Binv[r]*dot(eacc[r,:],W[j,:]) + b[j] ) )
__global__ void __launch_bounds__(512) edge_gemm(const float* __restrict__ W,
                                                 const float* __restrict__ b,
                                                 const float* __restrict__ ew) {
    __shared__ float Wt[HID * HID];   // Wt[k*64 + j] = W[j*64 + k]
    __shared__ float rsm[32 * HID];
    __shared__ float bsh[HID];

    int j   = threadIdx.x;
    int ty  = threadIdx.y;
    int tid = ty * 64 + j;

    for (int idx = tid; idx < HID * HID; idx += 512) {
        int jj = idx >> 6;
        int kk = idx & 63;
        Wt[kk * 64 + jj] = W[idx];
    }
    if (tid < HID) bsh[tid] = b[tid];

    int rowBase = blockIdx.x * 32;
    ((float4*)rsm)[tid] = ((const float4*)g_eacc)[rowBase * 16 + tid];
    __syncthreads();

    float acc0 = 0.f, acc1 = 0.f, acc2 = 0.f, acc3 = 0.f;
    const float4* r0 = (const float4*)&rsm[(ty)      * 64];
    const float4* r1 = (const float4*)&rsm[(ty + 8)  * 64];
    const float4* r2 = (const float4*)&rsm[(ty + 16) * 64];
    const float4* r3 = (const float4*)&rsm[(ty + 24) * 64];
    #pragma unroll
    for (int k4 = 0; k4 < 16; k4++) {
        float4 rv0 = r0[k4];
        float4 rv1 = r1[k4];
        float4 rv2 = r2[k4];
        float4 rv3 = r3[k4];
        float w0 = Wt[(k4 * 4 + 0) * 64 + j];
        float w1 = Wt[(k4 * 4 + 1) * 64 + j];
        float w2 = Wt[(k4 * 4 + 2) * 64 + j];
        float w3 = Wt[(k4 * 4 + 3) * 64 + j];
        acc0 = fmaf(rv0.x, w0, fmaf(rv0.y, w1, fmaf(rv0.z, w2, fmaf(rv0.w, w3, acc0))));
        acc1 = fmaf(rv1.x, w0, fmaf(rv1.y, w1, fmaf(rv1.z, w2, fmaf(rv1.w, w3, acc1))));
        acc2 = fmaf(rv2.x, w0, fmaf(rv2.y, w1, fmaf(rv2.z, w2, fmaf(rv2.w, w3, acc2))));
        acc3 = fmaf(rv3.x, w0, fmaf(rv3.y, w1, fmaf(rv3.z, w2, fmaf(rv3.w, w3, acc3))));
    }
    #pragma unroll
    for (int m = 0; m < 4; m++) {
        int row = rowBase + ty + m * 8;
        float acc = (m == 0) ? acc0 : (m == 1) ? acc1 : (m == 2) ? acc2 : acc3;
        float w = __ldg(&ew[row]);
        g_gh[row * HID + j] = __float2half(w * (g_Binv[row] * acc + bsh[j]));
    }
}

// edge -> node, writes fp16 x_next with relu (layers 0,1)
__global__ void __launch_bounds__(256) gather_en_h(__half* __restrict__ xout) {
    int t = blockIdx.x * blockDim.x + threadIdx.x;
    int n = t >> 3;
    int c = t & 7;
    unsigned mask = 0xFFu << (threadIdx.x & 24);
    int cnt = min(g_cntN[n], WN);
    float4 A, B;
    gather_row_ell(&g_csrN[n * WN], cnt, (const uint4*)g_gh + c, c, mask, A, B);
    float dv = g_Dinv[n];
    A.x = fmaxf(A.x * dv, 0.f); A.y = fmaxf(A.y * dv, 0.f);
    A.z = fmaxf(A.z * dv, 0.f); A.w = fmaxf(A.w * dv, 0.f);
    B.x = fmaxf(B.x * dv, 0.f); B.y = fmaxf(B.y * dv, 0.f);
    B.z = fmaxf(B.z * dv, 0.f); B.w = fmaxf(B.w * dv, 0.f);
    __half2 h0 = __floats2half2_rn(A.x, A.y);
    __half2 h1 = __floats2half2_rn(A.z, A.w);
    __half2 h2 = __floats2half2_rn(B.x, B.y);
    __half2 h3 = __floats2half2_rn(B.z, B.w);
    uint4 o;
    o.x = *reinterpret_cast<unsigned*>(&h0);
    o.y = *reinterpret_cast<unsigned*>(&h1);
    o.z = *reinterpret_cast<unsigned*>(&h2);
    o.w = *reinterpret_cast<unsigned*>(&h3);
    reinterpret_cast<uint4*>(xout)[n * 8 + c] = o;
}

// edge -> node, final layer: writes fp32 output, no relu
__global__ void __launch_bounds__(256) gather_en_f(float* __restrict__ xout) {
    int t = blockIdx.x * blockDim.x + threadIdx.x;
    int n = t >> 3;
    int c = t & 7;
    unsigned mask = 0xFFu << (threadIdx.x & 24);
    int cnt = min(g_cntN[n], WN);
    float4 A, B;
    gather_row_ell(&g_csrN[n * WN], cnt, (const uint4*)g_gh + c, c, mask, A, B);
    float dv = g_Dinv[n];
    A.x *= dv; A.y *= dv; A.z *= dv; A.w *= dv;
    B.x *= dv; B.y *= dv; B.z *= dv; B.w *= dv;
    float4* o = (float4*)xout + n * 16 + c * 2;
    o[0] = A;
    o[1] = B;
}

// ---------------- host -----------------------------------------------------
extern "C" void kernel_launch(void* const* d_in, const int* in_sizes, int n_in,
                              void* d_out, int out_size) {
    const int*   nidx = (const int*)d_in[0];
    const int*   eidx = nidx + NNZ;
    const float* ew   = (const float*)d_in[1];
    const float* emb  = (const float*)d_in[2];
    const float* W[3] = { (const float*)d_in[3], (const float*)d_in[5], (const float*)d_in[7] };
    const float* B[3] = { (const float*)d_in[4], (const float*)d_in[6], (const float*)d_in[8] };
    float* out = (float*)d_out;

    __half *x0, *x1, *x2;
    cudaGetSymbolAddress((void**)&x0, g_x0);
    cudaGetSymbolAddress((void**)&x1, g_x1);
    cudaGetSymbolAddress((void**)&x2, g_x2);

    fill_ell<<<cdiv(NNZ, 256), 256>>>(nidx, eidx);               // 1
    deg_inv<<<NUM_NODES * 8 / 256, 256>>>(ew);                    // 2
    convert_emb<<<NUM_NODES * 8 / 256, 256>>>((const float4*)emb);// 3

    const __half* xin[3] = { x0, x1, x2 };
    __half*       xh[2]  = { x1, x2 };

    for (int l = 0; l < 3; l++) {
        gather_ne_h<<<NUM_EDGES * 8 / 256, 256>>>(xin[l]);        // l=0 -> launch 4 (profiled)
        edge_gemm<<<NUM_EDGES / 32, dim3(64, 8)>>>(W[l], B[l], ew);
        if (l < 2) gather_en_h<<<NUM_NODES * 8 / 256, 256>>>(xh[l]);
        else       gather_en_f<<<NUM_NODES * 8 / 256, 256>>>(out);
    }

    cleanup_kernel<<<cdiv(NUM_NODES, 256), 256>>>();
}

// round 16
// speedup vs baseline: 1.0174x; 1.0174x over previous
#include <cuda_runtime.h>
#include <cuda_fp16.h>

#define NNZ        2000000
#define NUM_NODES  200000
#define NUM_EDGES  100000
#define HID        64
#define L_TOT      (NUM_EDGES + NUM_NODES)          // 300000
#define NB_SCAN    ((L_TOT + 1023) / 1024)          // 293

// ---------------- scratch (device globals; zero-initialized at load) -------
// Invariant: g_cnt is ZERO at the start of every kernel_launch
// (module-load zeros; re-zeroed by cleanup_kernel at the end of every launch).
__device__ __half g_x0[NUM_NODES * HID];    // fp16 copy of emb
__device__ __half g_x1[NUM_NODES * HID];
__device__ __half g_x2[NUM_NODES * HID];
__device__ __half g_gh[NUM_EDGES * HID];    // fp16 edge features after GEMM
__device__ float  g_eacc[NUM_EDGES * HID];  // fp32 node->edge accumulator
__device__ float  g_Dinv[NUM_NODES];
__device__ float  g_Binv[NUM_EDGES];
__device__ int    g_cnt[L_TOT];             // [0,E): edge counts, [E,E+N): node counts
__device__ int    g_off[L_TOT + 1];         // concatenated offsets; node seg starts at NNZ
__device__ int    g_cur[L_TOT];
__device__ int    g_csr[2 * NNZ];           // [0,NNZ): node ids by edge; [NNZ,2NNZ): edge ids by node
__device__ int    g_sums[512];

static inline int cdiv(int a, int b) { return (a + b - 1) / b; }

// ---------------- CSR construction ----------------------------------------
__global__ void hist_kernel(const int* __restrict__ nidx,
                            const int* __restrict__ eidx) {
    int i = blockIdx.x * blockDim.x + threadIdx.x;
    if (i < NNZ) {
        atomicAdd(&g_cnt[eidx[i]], 1);
        atomicAdd(&g_cnt[NUM_EDGES + nidx[i]], 1);
    }
}

// Coalesced per-block exclusive scan (1024 elements/block).
__global__ void scan_block_k() {
    __shared__ int sh[1024];
    int t = threadIdx.x;
    int i = blockIdx.x * 1024 + t;
    int v = (i < L_TOT) ? g_cnt[i] : 0;
    sh[t] = v;
    __syncthreads();
    for (int off = 1; off < 1024; off <<= 1) {
        int u = (t >= off) ? sh[t - off] : 0;
        __syncthreads();
        sh[t] += u;
        __syncthreads();
    }
    if (i < L_TOT) g_off[i] = sh[t] - v;
    if (t == 1023) g_sums[blockIdx.x] = sh[1023];
}

// Each block scans the 293 partial sums in shared, applies its prefix.
__global__ void scan_add_k() {
    __shared__ int sh[512];
    int t = threadIdx.x;
    if (t < 512) sh[t] = (t < NB_SCAN) ? g_sums[t] : 0;
    __syncthreads();
    for (int off = 1; off < 512; off <<= 1) {
        int u = (t >= off && t < 512) ? sh[t - off] : 0;
        __syncthreads();
        if (t < 512) sh[t] += u;
        __syncthreads();
    }
    int prefix = (blockIdx.x == 0) ? 0 : sh[blockIdx.x - 1];
    int i = blockIdx.x * 1024 + t;
    if (i < L_TOT) {
        int v = g_off[i] + prefix;
        g_off[i] = v;
        g_cur[i] = v;
    }
    if (i == 0) g_off[L_TOT] = 2 * NNZ;
}

__global__ void fill_kernel(const int* __restrict__ nidx,
                            const int* __restrict__ eidx) {
    int i = blockIdx.x * blockDim.x + threadIdx.x;
    if (i < NNZ) {
        int n = nidx[i];
        int e = eidx[i];
        int p = atomicAdd(&g_cur[e], 1);
        g_csr[p] = n;
        int q = atomicAdd(&g_cur[NUM_EDGES + n], 1);
        g_csr[q] = e;
    }
}

// Dinv via packed-CSR ew-gather (8 lanes/node) + Binv from edge counts.
__global__ void deg_inv(const float* __restrict__ ew) {
    int t = blockIdx.x * blockDim.x + threadIdx.x;   // NUM_NODES*8 threads
    int n = t >> 3;
    int c = t & 7;
    int k0 = g_off[NUM_EDGES + n];
    int k1 = g_off[NUM_EDGES + n + 1];
    float s = 0.f;
    for (int j = k0 + c; j < k1; j += 8)
        s += __ldg(&ew[g_csr[j]]);
    #pragma unroll
    for (int off = 4; off; off >>= 1)
        s += __shfl_down_sync(0xFFFFFFFFu, s, off, 8);
    if (c == 0) g_Dinv[n] = s > 0.f ? 1.f / s : 0.f;
    if (t < NUM_EDGES) {
        int b = g_cnt[t];
        g_Binv[t] = b > 0 ? 1.f / (float)b : 0.f;
    }
}

// emb fp32 -> x0 fp16 (one thread per 8 elements)
__global__ void convert_emb(const float4* __restrict__ emb4) {
    int i = blockIdx.x * blockDim.x + threadIdx.x;
    if (i < NUM_NODES * 8) {
        float4 u = __ldg(&emb4[2 * i]);
        float4 v = __ldg(&emb4[2 * i + 1]);
        __half2 h0 = __floats2half2_rn(u.x, u.y);
        __half2 h1 = __floats2half2_rn(u.z, u.w);
        __half2 h2 = __floats2half2_rn(v.x, v.y);
        __half2 h3 = __floats2half2_rn(v.z, v.w);
        uint4 o;
        o.x = *reinterpret_cast<unsigned*>(&h0);
        o.y = *reinterpret_cast<unsigned*>(&h1);
        o.z = *reinterpret_cast<unsigned*>(&h2);
        o.w = *reinterpret_cast<unsigned*>(&h3);
        reinterpret_cast<uint4*>(g_x0)[i] = o;
    }
}

// End-of-launch cleanup: restore the zero invariant for the next replay.
__global__ void cleanup_kernel() {
    int i = blockIdx.x * blockDim.x + threadIdx.x;
    if (i < L_TOT) g_cnt[i] = 0;
}

// ---------------- gather core (fp16 rows, 8 lanes/row) ---------------------
// fp32 convert+accumulate of one uint4 (8 halves) into A,B
#define ACCH(A, B, v) {                                                   \
    __half2* hh = reinterpret_cast<__half2*>(&(v));                       \
    float2 f0 = __half22float2(hh[0]); float2 f1 = __half22float2(hh[1]); \
    float2 f2 = __half22float2(hh[2]); float2 f3 = __half22float2(hh[3]); \
    A.x += f0.x; A.y += f0.y; A.z += f1.x; A.w += f1.y;                   \
    B.x += f2.x; B.y += f2.y; B.z += f3.x; B.w += f3.y; }

// vector half2 add of two uint4s (4x HADD2)
__device__ __forceinline__ uint4 hadd2x4(uint4 a, uint4 b) {
    __half2* pa = reinterpret_cast<__half2*>(&a);
    __half2* pb = reinterpret_cast<__half2*>(&b);
    uint4 r;
    __half2* pr = reinterpret_cast<__half2*>(&r);
    pr[0] = __hadd2(pa[0], pb[0]);
    pr[1] = __hadd2(pa[1], pb[1]);
    pr[2] = __hadd2(pa[2], pb[2]);
    pr[3] = __hadd2(pa[3], pb[3]);
    return r;
}

// Lanes 0-3 load batch indices, broadcast via width-8 shfl.
// 4 rows per iteration combined with a depth-2 fp16 tree, then one fp32 add.
__device__ __forceinline__ void gather_row_h(const int* __restrict__ csr,
                                             const uint4* __restrict__ src,
                                             int k, int en, int c, unsigned mask,
                                             float4& A, float4& B) {
    A = make_float4(0.f, 0.f, 0.f, 0.f);
    B = A;
    int my = 0;
    if (k + 4 <= en) {
        if (c < 4) my = __ldg(&csr[k + c]);
        while (k + 4 <= en) {
            int i0 = __shfl_sync(mask, my, 0, 8);
            int i1 = __shfl_sync(mask, my, 1, 8);
            int i2 = __shfl_sync(mask, my, 2, 8);
            int i3 = __shfl_sync(mask, my, 3, 8);
            int kn = k + 4;
            if (kn + 4 <= en && c < 4) my = __ldg(&csr[kn + c]);
            uint4 v0 = __ldg(src + i0 * 8);
            uint4 v1 = __ldg(src + i1 * 8);
            uint4 v2 = __ldg(src + i2 * 8);
            uint4 v3 = __ldg(src + i3 * 8);
            uint4 s = hadd2x4(hadd2x4(v0, v1), hadd2x4(v2, v3));
            ACCH(A, B, s);
            k = kn;
        }
    }
    for (; k < en; k++) {
        int i0 = __ldg(&csr[k]);
        uint4 v = __ldg(src + i0 * 8);
        ACCH(A, B, v);
    }
}

// node -> edge: eacc[e] (fp32) = sum of fp16 x rows
__global__ void __launch_bounds__(256) gather_ne_h(const __half* __restrict__ x) {
    int t = blockIdx.x * blockDim.x + threadIdx.x;
    int e = t >> 3;
    int c = t & 7;
    unsigned mask = 0xFFu << (threadIdx.x & 24);
    int k  = g_off[e];
    int en = g_off[e + 1];
    float4 A, B;
    gather_row_h(g_csr, (const uint4*)x + c, k, en, c, mask, A, B);
    float4* o = (float4*)g_eacc + e * 16 + c * 2;
    o[0] = A;
    o[1] = B;
}

// edge GEMM: g_gh[r][j] = fp16( ew[r] * ( Binv[r]*dot(eacc[r,:],W[j,:]) + b[j] ) )
__global__ void __launch_bounds__(512) edge_gemm(const float* __restrict__ W,
                                                 const float* __restrict__ b,
                                                 const float* __restrict__ ew) {
    __shared__ float Wt[HID * HID];   // Wt[k*64 + j] = W[j*64 + k]
    __shared__ float rsm[32 * HID];
    __shared__ float bsh[HID];

    int j   = threadIdx.x;
    int ty  = threadIdx.y;
    int tid = ty * 64 + j;

    for (int idx = tid; idx < HID * HID; idx += 512) {
        int jj = idx >> 6;
        int kk = idx & 63;
        Wt[kk * 64 + jj] = W[idx];
    }
    if (tid < HID) bsh[tid] = b[tid];

    int rowBase = blockIdx.x * 32;
    ((float4*)rsm)[tid] = ((const float4*)g_eacc)[rowBase * 16 + tid];
    __syncthreads();

    float acc0 = 0.f, acc1 = 0.f, acc2 = 0.f, acc3 = 0.f;
    const float4* r0 = (const float4*)&rsm[(ty)      * 64];
    const float4* r1 = (const float4*)&rsm[(ty + 8)  * 64];
    const float4* r2 = (const float4*)&rsm[(ty + 16) * 64];
    const float4* r3 = (const float4*)&rsm[(ty + 24) * 64];
    #pragma unroll
    for (int k4 = 0; k4 < 16; k4++) {
        float4 rv0 = r0[k4];
        float4 rv1 = r1[k4];
        float4 rv2 = r2[k4];
        float4 rv3 = r3[k4];
        float w0 = Wt[(k4 * 4 + 0) * 64 + j];
        float w1 = Wt[(k4 * 4 + 1) * 64 + j];
        float w2 = Wt[(k4 * 4 + 2) * 64 + j];
        float w3 = Wt[(k4 * 4 + 3) * 64 + j];
        acc0 = fmaf(rv0.x, w0, fmaf(rv0.y, w1, fmaf(rv0.z, w2, fmaf(rv0.w, w3, acc0))));
        acc1 = fmaf(rv1.x, w0, fmaf(rv1.y, w1, fmaf(rv1.z, w2, fmaf(rv1.w, w3, acc1))));
        acc2 = fmaf(rv2.x, w0, fmaf(rv2.y, w1, fmaf(rv2.z, w2, fmaf(rv2.w, w3, acc2))));
        acc3 = fmaf(rv3.x, w0, fmaf(rv3.y, w1, fmaf(rv3.z, w2, fmaf(rv3.w, w3, acc3))));
    }
    #pragma unroll
    for (int m = 0; m < 4; m++) {
        int row = rowBase + ty + m * 8;
        float acc = (m == 0) ? acc0 : (m == 1) ? acc1 : (m == 2) ? acc2 : acc3;
        float w = __ldg(&ew[row]);
        g_gh[row * HID + j] = __float2half(w * (g_Binv[row] * acc + bsh[j]));
    }
}

// edge -> node, writes fp16 x_next with relu (layers 0,1)
__global__ void __launch_bounds__(256) gather_en_h(__half* __restrict__ xout) {
    int t = blockIdx.x * blockDim.x + threadIdx.x;
    int n = t >> 3;
    int c = t & 7;
    unsigned mask = 0xFFu << (threadIdx.x & 24);
    int k  = g_off[NUM_EDGES + n];
    int en = g_off[NUM_EDGES + n + 1];
    float4 A, B;
    gather_row_h(g_csr, (const uint4*)g_gh + c, k, en, c, mask, A, B);
    float dv = g_Dinv[n];
    A.x = fmaxf(A.x * dv, 0.f); A.y = fmaxf(A.y * dv, 0.f);
    A.z = fmaxf(A.z * dv, 0.f); A.w = fmaxf(A.w * dv, 0.f);
    B.x = fmaxf(B.x * dv, 0.f); B.y = fmaxf(B.y * dv, 0.f);
    B.z = fmaxf(B.z * dv, 0.f); B.w = fmaxf(B.w * dv, 0.f);
    __half2 h0 = __floats2half2_rn(A.x, A.y);
    __half2 h1 = __floats2half2_rn(A.z, A.w);
    __half2 h2 = __floats2half2_rn(B.x, B.y);
    __half2 h3 = __floats2half2_rn(B.z, B.w);
    uint4 o;
    o.x = *reinterpret_cast<unsigned*>(&h0);
    o.y = *reinterpret_cast<unsigned*>(&h1);
    o.z = *reinterpret_cast<unsigned*>(&h2);
    o.w = *reinterpret_cast<unsigned*>(&h3);
    reinterpret_cast<uint4*>(xout)[n * 8 + c] = o;
}

// edge -> node, final layer: writes fp32 output, no relu
__global__ void __launch_bounds__(256) gather_en_f(float* __restrict__ xout) {
    int t = blockIdx.x * blockDim.x + threadIdx.x;
    int n = t >> 3;
    int c = t & 7;
    unsigned mask = 0xFFu << (threadIdx.x & 24);
    int k  = g_off[NUM_EDGES + n];
    int en = g_off[NUM_EDGES + n + 1];
    float4 A, B;
    gather_row_h(g_csr, (const uint4*)g_gh + c, k, en, c, mask, A, B);
    float dv = g_Dinv[n];
    A.x *= dv; A.y *= dv; A.z *= dv; A.w *= dv;
    B.x *= dv; B.y *= dv; B.z *= dv; B.w *= dv;
    float4* o = (float4*)xout + n * 16 + c * 2;
    o[0] = A;
    o[1] = B;
}

// ---------------- host -----------------------------------------------------
extern "C" void kernel_launch(void* const* d_in, const int* in_sizes, int n_in,
                              void* d_out, int out_size) {
    const int*   nidx = (const int*)d_in[0];
    const int*   eidx = nidx + NNZ;
    const float* ew   = (const float*)d_in[1];
    const float* emb  = (const float*)d_in[2];
    const float* W[3] = { (const float*)d_in[3], (const float*)d_in[5], (const float*)d_in[7] };
    const float* B[3] = { (const float*)d_in[4], (const float*)d_in[6], (const float*)d_in[8] };
    float* out = (float*)d_out;

    __half *x0, *x1, *x2;
    cudaGetSymbolAddress((void**)&x0, g_x0);
    cudaGetSymbolAddress((void**)&x1, g_x1);
    cudaGetSymbolAddress((void**)&x2, g_x2);

    hist_kernel<<<cdiv(NNZ, 256), 256>>>(nidx, eidx);             // 1
    scan_block_k<<<NB_SCAN, 1024>>>();                             // 2
    scan_add_k<<<NB_SCAN, 1024>>>();                               // 3
    fill_kernel<<<cdiv(NNZ, 256), 256>>>(nidx, eidx);              // 4 (profiled)
    deg_inv<<<NUM_NODES * 8 / 256, 256>>>(ew);                     // 5
    convert_emb<<<NUM_NODES * 8 / 256, 256>>>((const float4*)emb); // 6

    const __half* xin[3] = { x0, x1, x2 };
    __half*       xh[2]  = { x1, x2 };

    for (int l = 0; l < 3; l++) {
        gather_ne_h<<<NUM_EDGES * 8 / 256, 256>>>(xin[l]);
        edge_gemm<<<NUM_EDGES / 32, dim3(64, 8)>>>(W[l], B[l], ew);
        if (l < 2) gather_en_h<<<NUM_NODES * 8 / 256, 256>>>(xh[l]);
        else       gather_en_f<<<NUM_NODES * 8 / 256, 256>>>(out);
    }

    cleanup_kernel<<<cdiv(L_TOT, 256), 256>>>();
}